// round 1
// baseline (speedup 1.0000x reference)
#include <cuda_runtime.h>
#include <cuda_bf16.h>
#include <math.h>
#include <stdint.h>

// Problem constants
#define Bb   64
#define Dd   512
#define Vv   512
#define Oo   720
#define Ee   8
#define NTOK    (Bb*Vv)        // 32768 tokens
#define NASSIGN (NTOK*2)       // 65536 (token,expert) assignments (top_k = 2)
#define TILE_M  128
#define MAX_TILES (NASSIGN/TILE_M + Ee)   // 520 (each expert padded to 128)
#define ROWS_CAP  (MAX_TILES*TILE_M)
#define SA 36                  // smem row stride (floats), 16B-aligned, conflict-free frags

// ---------------- static device scratch (no allocations allowed) ----------------
__device__ float g_XT[NTOK*Dd];          // tokens row-major [B*V][D], tf32-rounded (64 MB)
__device__ float g_We[Ee*Oo*Dd];         // tf32-rounded expert weights (11.8 MB)
__device__ float g_part[2][NTOK*Oo];     // per-top-k-slot partial outputs (2 x 94 MB)
__device__ int   g_rows[ROWS_CAP];       // assignment row -> token*2+slot (-1 = pad)
__device__ float g_roww[ROWS_CAP];       // assignment row -> combine weight
__device__ int   g_counts[Ee];
__device__ int   g_cursor[Ee];
__device__ int   g_tile_e[MAX_TILES];
__device__ int   g_tile_r0[MAX_TILES];
__device__ int   g_ntiles;
__device__ int   g_sel[NASSIGN];
__device__ float g_wsel[NASSIGN];

__device__ __forceinline__ float to_tf32(float x) {
    float r;
    asm("cvt.rna.tf32.f32 %0, %1;" : "=f"(r) : "f"(x));
    return r;
}

// ---------------- K0: round We to tf32 copy; reset counters ----------------
__global__ void k0_prep(const float* __restrict__ We) {
    int i = blockIdx.x * blockDim.x + threadIdx.x;
    if (i < Ee*Oo*Dd) g_We[i] = to_tf32(We[i]);
    if (blockIdx.x == 0 && threadIdx.x < Ee) g_counts[threadIdx.x] = 0;
}

// ---------------- K1: fused transpose + gating + softmax + top-2 ----------------
// grid (V/128, B), block 128. Each thread owns one token (v = v0 + tid).
__global__ void k1_gate(const float* __restrict__ x, const float* __restrict__ Wg) {
    __shared__ float sWg[Ee*Dd];          // 16 KB
    __shared__ float sX[32][129];         // 16.5 KB, padded
    const int b  = blockIdx.y;
    const int v0 = blockIdx.x * 128;
    const int tid = threadIdx.x;
    const int wq = tid >> 5, lane = tid & 31;

    for (int i = tid; i < Ee*Dd; i += 128) sWg[i] = Wg[i];
    __syncthreads();

    float lg[Ee];
#pragma unroll
    for (int e = 0; e < Ee; e++) lg[e] = 0.f;

    for (int dc = 0; dc < Dd/32; dc++) {
        // coalesced load of x[b, dc*32 .. +32, v0 .. v0+128]
#pragma unroll
        for (int i = 0; i < 32; i++)
            sX[i][tid] = x[((size_t)b*Dd + dc*32 + i)*Vv + v0 + tid];
        __syncthreads();
        // gating logits: thread = token v0+tid
#pragma unroll
        for (int i = 0; i < 32; i++) {
            float xv = sX[i][tid];
            int d = dc*32 + i;
#pragma unroll
            for (int e = 0; e < Ee; e++) lg[e] += xv * sWg[e*Dd + d];
        }
        // transpose-write XT (coalesced along d), tf32-rounded.
        // warp wq writes tokens v = wq*32 .. +32; lane = local d. stride-129 smem reads: conflict-free.
#pragma unroll
        for (int r = 0; r < 32; r++) {
            int v = wq*32 + r;
            g_XT[((size_t)(b*Vv + v0 + v))*Dd + dc*32 + lane] = to_tf32(sX[lane][v]);
        }
        __syncthreads();
    }

    // softmax (fp32, matches reference routing) + top-2 with lowest-index tie-break
    float m = lg[0];
#pragma unroll
    for (int e = 1; e < Ee; e++) m = fmaxf(m, lg[e]);
    float p[Ee], s = 0.f;
#pragma unroll
    for (int e = 0; e < Ee; e++) { p[e] = expf(lg[e] - m); s += p[e]; }
    float inv = 1.f / s;
#pragma unroll
    for (int e = 0; e < Ee; e++) p[e] *= inv;

    int i1 = 0;
#pragma unroll
    for (int e = 1; e < Ee; e++) if (p[e] > p[i1]) i1 = e;
    int i2 = (i1 == 0) ? 1 : 0;
#pragma unroll
    for (int e = 0; e < Ee; e++) if (e != i1 && p[e] > p[i2]) i2 = e;

    int t = b*Vv + v0 + tid;
    g_sel[2*t + 0] = i1;  g_wsel[2*t + 0] = p[i1];
    g_sel[2*t + 1] = i2;  g_wsel[2*t + 1] = p[i2];
    atomicAdd(&g_counts[i1], 1);
    atomicAdd(&g_counts[i2], 1);
}

// ---------------- K2: plan tiles (single thread; tiny) ----------------
__global__ void k2_plan() {
    if (threadIdx.x != 0 || blockIdx.x != 0) return;
    int base = 0, nt = 0;
    for (int e = 0; e < Ee; e++) {
        int cnt = g_counts[e];
        g_cursor[e] = base;
        int t = (cnt + TILE_M - 1) / TILE_M;
        for (int i = 0; i < t; i++) { g_tile_e[nt] = e; g_tile_r0[nt] = base + i*TILE_M; nt++; }
        for (int pq = base + cnt; pq < base + t*TILE_M; pq++) g_rows[pq] = -1; // pads
        base += t*TILE_M;
    }
    g_ntiles = nt;
}

// ---------------- K3: scatter assignments into expert-sorted rows ----------------
__global__ void k3_scatter() {
    int t = blockIdx.x * blockDim.x + threadIdx.x;
    if (t >= NTOK) return;
#pragma unroll
    for (int s = 0; s < 2; s++) {
        int e = g_sel[2*t + s];
        int pos = atomicAdd(&g_cursor[e], 1);
        g_rows[pos] = 2*t + s;
        g_roww[pos] = g_wsel[2*t + s];
    }
}

// ---------------- K4: grouped GEMM, tf32 mma.sync, 128x128 CTA tile ----------------
// grid (MAX_TILES, ceil(O/128)), block 256 (8 warps, 4(M) x 2(N) layout)
__global__ __launch_bounds__(256) void k4_gemm(const float* __restrict__ be) {
    if ((int)blockIdx.x >= g_ntiles) return;
    const int mt = blockIdx.x;
    const int o0 = blockIdx.y * 128;

    __shared__ __align__(16) float As[TILE_M*SA];
    __shared__ __align__(16) float Bs[128*SA];
    __shared__ int   sTok[TILE_M];
    __shared__ float sW[TILE_M];
    __shared__ float sBias[128];

    const int tid  = threadIdx.x;
    const int lane = tid & 31, w = tid >> 5;
    const int wm = w & 3, wn = w >> 2;          // warp tile: rows wm*32, cols wn*64
    const int g  = lane >> 2, tg = lane & 3;    // mma fragment coords

    const int e  = g_tile_e[mt];
    const int r0 = g_tile_r0[mt];
    const float* WeE = g_We + (size_t)e*Oo*Dd;

    if (tid < TILE_M) { sTok[tid] = g_rows[r0 + tid]; sW[tid] = g_roww[r0 + tid]; }
    if (tid < 128) { int o = o0 + tid; sBias[tid] = (o < Oo) ? be[e*Oo + o] : 0.f; }
    __syncthreads();

    float acc[2][8][4];
#pragma unroll
    for (int mf = 0; mf < 2; mf++)
#pragma unroll
        for (int nf = 0; nf < 8; nf++)
#pragma unroll
            for (int i = 0; i < 4; i++) acc[mf][nf][i] = 0.f;

    for (int kc = 0; kc < Dd/32; kc++) {
        // load 128x32 A (gathered token rows) and 128x32 B (expert weights), float4, zero-fill pads
#pragma unroll
        for (int j = 0; j < 4; j++) {
            int q = tid + j*256;          // 0..1023
            int r = q >> 3;
            int fc = (q & 7) * 4;
            int tk = sTok[r];
            float4 va = make_float4(0.f, 0.f, 0.f, 0.f);
            if (tk >= 0) va = *(const float4*)(g_XT + (size_t)(tk >> 1)*Dd + kc*32 + fc);
            *(float4*)(As + r*SA + fc) = va;
            int o = o0 + r;
            float4 vb = make_float4(0.f, 0.f, 0.f, 0.f);
            if (o < Oo) vb = *(const float4*)(WeE + (size_t)o*Dd + kc*32 + fc);
            *(float4*)(Bs + r*SA + fc) = vb;
        }
        __syncthreads();

#pragma unroll
        for (int ks = 0; ks < 4; ks++) {
            const int k0 = ks*8;
            uint32_t a[2][4], bf[8][2];
#pragma unroll
            for (int mf = 0; mf < 2; mf++) {
                int rb = wm*32 + mf*16;
                a[mf][0] = __float_as_uint(As[(rb +     g)*SA + k0 +     tg]);
                a[mf][1] = __float_as_uint(As[(rb + 8 + g)*SA + k0 +     tg]);
                a[mf][2] = __float_as_uint(As[(rb +     g)*SA + k0 + 4 + tg]);
                a[mf][3] = __float_as_uint(As[(rb + 8 + g)*SA + k0 + 4 + tg]);
            }
#pragma unroll
            for (int nf = 0; nf < 8; nf++) {
                int nb = wn*64 + nf*8;
                bf[nf][0] = __float_as_uint(Bs[(nb + g)*SA + k0 +     tg]);
                bf[nf][1] = __float_as_uint(Bs[(nb + g)*SA + k0 + 4 + tg]);
            }
#pragma unroll
            for (int mf = 0; mf < 2; mf++)
#pragma unroll
                for (int nf = 0; nf < 8; nf++) {
                    float* c = acc[mf][nf];
                    asm volatile(
                        "mma.sync.aligned.m16n8k8.row.col.f32.tf32.tf32.f32 "
                        "{%0,%1,%2,%3}, {%4,%5,%6,%7}, {%8,%9}, {%0,%1,%2,%3};\n"
                        : "+f"(c[0]), "+f"(c[1]), "+f"(c[2]), "+f"(c[3])
                        : "r"(a[mf][0]), "r"(a[mf][1]), "r"(a[mf][2]), "r"(a[mf][3]),
                          "r"(bf[nf][0]), "r"(bf[nf][1]));
                }
        }
        __syncthreads();
    }

    // epilogue: out = coef * (acc + bias), float2 stores into slot-partial buffer
#pragma unroll
    for (int mf = 0; mf < 2; mf++) {
#pragma unroll
        for (int nf = 0; nf < 8; nf++) {
            int c = wn*64 + nf*8 + tg*2;
            int o = o0 + c;
            if (o >= Oo) continue;
#pragma unroll
            for (int h = 0; h < 2; h++) {
                int r = wm*32 + mf*16 + g + h*8;
                int tk = sTok[r];
                if (tk < 0) continue;
                float wv = sW[r];
                float2 v;
                v.x = wv * (acc[mf][nf][h*2 + 0] + sBias[c]);
                v.y = wv * (acc[mf][nf][h*2 + 1] + sBias[c + 1]);
                *(float2*)(&g_part[tk & 1][(size_t)(tk >> 1)*Oo + o]) = v;
            }
        }
    }
}

// ---------------- K5: sum two slot partials + transpose [B,V,O] -> [B,O,V] ----------------
// grid (V/32, ceil(O/32), B), block (32,8)
__global__ void k5_out(float* __restrict__ out) {
    __shared__ float s[32][33];
    const int b = blockIdx.z, v0 = blockIdx.x*32, o0 = blockIdx.y*32;
    const int tx = threadIdx.x, ty = threadIdx.y;
#pragma unroll
    for (int i = 0; i < 4; i++) {
        int vy = ty + i*8;
        int o = o0 + tx;
        if (o < Oo) {
            size_t idx = (size_t)(b*Vv + v0 + vy)*Oo + o;
            s[vy][tx] = g_part[0][idx] + g_part[1][idx];
        }
    }
    __syncthreads();
#pragma unroll
    for (int i = 0; i < 4; i++) {
        int oy = ty + i*8;
        if (o0 + oy < Oo)
            out[((size_t)b*Oo + o0 + oy)*Vv + v0 + tx] = s[tx][oy];
    }
}

// ---------------- launch ----------------
extern "C" void kernel_launch(void* const* d_in, const int* in_sizes, int n_in,
                              void* d_out, int out_size) {
    const float* x  = (const float*)d_in[0];
    const float* Wg = (const float*)d_in[1];
    const float* We = (const float*)d_in[2];
    const float* be = (const float*)d_in[3];
    float* out = (float*)d_out;

    k0_prep<<<(Ee*Oo*Dd + 1023)/1024, 1024>>>(We);
    k1_gate<<<dim3(Vv/128, Bb), 128>>>(x, Wg);
    k2_plan<<<1, 32>>>();
    k3_scatter<<<(NTOK + 255)/256, 256>>>();
    k4_gemm<<<dim3(MAX_TILES, (Oo + 127)/128), 256>>>(be);
    k5_out<<<dim3(Vv/32, (Oo + 31)/32, Bb), dim3(32, 8)>>>(out);
}

// round 2
// speedup vs baseline: 1.5236x; 1.5236x over previous
#include <cuda_runtime.h>
#include <cuda_bf16.h>
#include <math.h>
#include <stdint.h>

// Problem constants
#define Bb   64
#define Dd   512
#define Vv   512
#define Oo   720
#define Ee   8
#define NTOK    (Bb*Vv)        // 32768 tokens
#define NASSIGN (NTOK*2)       // 65536 assignments (top_k = 2)
#define TILE_M  128
#define TILE_N  144            // 720 = 5 * 144, exact
#define MAX_TILES (NASSIGN/TILE_M + Ee)   // 520
#define ROWS_CAP  (MAX_TILES*TILE_M)
#define SA 36                  // smem row stride (floats), 16B-aligned, conflict-free
#define STAGE_FLOATS ((TILE_M + TILE_N) * SA)   // 9792 floats = 39168 B
#define NSTAGE 3
#define NKCHUNK (Dd/32)        // 16

// ---------------- static device scratch ----------------
__device__ float g_XT[NTOK*Dd];          // tokens [B*V][D], tf32-rounded
__device__ float g_We[Ee*Oo*Dd];         // tf32-rounded expert weights
__device__ float g_part[2][NTOK*Oo];     // per-slot partial outputs
__device__ int   g_rows[ROWS_CAP];
__device__ float g_roww[ROWS_CAP];
__device__ int   g_counts[Ee];
__device__ int   g_cursor[Ee];
__device__ int   g_tile_e[MAX_TILES];
__device__ int   g_tile_r0[MAX_TILES];
__device__ int   g_ntiles;
__device__ int   g_sel[NASSIGN];
__device__ float g_wsel[NASSIGN];

__device__ __forceinline__ float to_tf32(float x) {
    float r;
    asm("cvt.rna.tf32.f32 %0, %1;" : "=f"(r) : "f"(x));
    return r;
}

__device__ __forceinline__ void cp16(float* smem_ptr, const float* gptr, bool valid) {
    uint32_t saddr = (uint32_t)__cvta_generic_to_shared(smem_ptr);
    int sz = valid ? 16 : 0;
    asm volatile("cp.async.cg.shared.global [%0], [%1], 16, %2;\n"
                 :: "r"(saddr), "l"(gptr), "r"(sz));
}

// ---------------- K0: round We to tf32 copy; reset counters ----------------
__global__ void k0_prep(const float* __restrict__ We) {
    int i = blockIdx.x * blockDim.x + threadIdx.x;
    if (i < Ee*Oo*Dd) g_We[i] = to_tf32(We[i]);
    if (blockIdx.x == 0 && threadIdx.x < Ee) g_counts[threadIdx.x] = 0;
}

// ---------------- K1: fused transpose + gating + softmax + top-2 ----------------
__global__ void k1_gate(const float* __restrict__ x, const float* __restrict__ Wg) {
    __shared__ float sWg[Ee*Dd];
    __shared__ float sX[32][129];
    const int b  = blockIdx.y;
    const int v0 = blockIdx.x * 128;
    const int tid = threadIdx.x;
    const int wq = tid >> 5, lane = tid & 31;

    for (int i = tid; i < Ee*Dd; i += 128) sWg[i] = Wg[i];
    __syncthreads();

    float lg[Ee];
#pragma unroll
    for (int e = 0; e < Ee; e++) lg[e] = 0.f;

    for (int dc = 0; dc < Dd/32; dc++) {
#pragma unroll
        for (int i = 0; i < 32; i++)
            sX[i][tid] = x[((size_t)b*Dd + dc*32 + i)*Vv + v0 + tid];
        __syncthreads();
#pragma unroll
        for (int i = 0; i < 32; i++) {
            float xv = sX[i][tid];
            int d = dc*32 + i;
#pragma unroll
            for (int e = 0; e < Ee; e++) lg[e] += xv * sWg[e*Dd + d];
        }
#pragma unroll
        for (int r = 0; r < 32; r++) {
            int v = wq*32 + r;
            g_XT[((size_t)(b*Vv + v0 + v))*Dd + dc*32 + lane] = to_tf32(sX[lane][v]);
        }
        __syncthreads();
    }

    float m = lg[0];
#pragma unroll
    for (int e = 1; e < Ee; e++) m = fmaxf(m, lg[e]);
    float p[Ee], s = 0.f;
#pragma unroll
    for (int e = 0; e < Ee; e++) { p[e] = expf(lg[e] - m); s += p[e]; }
    float inv = 1.f / s;
#pragma unroll
    for (int e = 0; e < Ee; e++) p[e] *= inv;

    int i1 = 0;
#pragma unroll
    for (int e = 1; e < Ee; e++) if (p[e] > p[i1]) i1 = e;
    int i2 = (i1 == 0) ? 1 : 0;
#pragma unroll
    for (int e = 0; e < Ee; e++) if (e != i1 && p[e] > p[i2]) i2 = e;

    int t = b*Vv + v0 + tid;
    g_sel[2*t + 0] = i1;  g_wsel[2*t + 0] = p[i1];
    g_sel[2*t + 1] = i2;  g_wsel[2*t + 1] = p[i2];
    atomicAdd(&g_counts[i1], 1);
    atomicAdd(&g_counts[i2], 1);
}

// ---------------- K2: plan tiles ----------------
__global__ void k2_plan() {
    if (threadIdx.x != 0 || blockIdx.x != 0) return;
    int base = 0, nt = 0;
    for (int e = 0; e < Ee; e++) {
        int cnt = g_counts[e];
        g_cursor[e] = base;
        int t = (cnt + TILE_M - 1) / TILE_M;
        for (int i = 0; i < t; i++) { g_tile_e[nt] = e; g_tile_r0[nt] = base + i*TILE_M; nt++; }
        for (int pq = base + cnt; pq < base + t*TILE_M; pq++) g_rows[pq] = -1;
        base += t*TILE_M;
    }
    g_ntiles = nt;
}

// ---------------- K3: scatter assignments ----------------
__global__ void k3_scatter() {
    int t = blockIdx.x * blockDim.x + threadIdx.x;
    if (t >= NTOK) return;
#pragma unroll
    for (int s = 0; s < 2; s++) {
        int e = g_sel[2*t + s];
        int pos = atomicAdd(&g_cursor[e], 1);
        g_rows[pos] = 2*t + s;
        g_roww[pos] = g_wsel[2*t + s];
    }
}

// ---------------- K4: grouped GEMM, tf32 mma.sync, 128x144 CTA, 3-stage cp.async ----------------
// grid (5, MAX_TILES): n-tiles fastest so one m-tile's A rows stay hot in L2.
__global__ __launch_bounds__(256) void k4_gemm(const float* __restrict__ be) {
    const int mt = blockIdx.y;
    if (mt >= g_ntiles) return;
    const int o0 = blockIdx.x * TILE_N;

    extern __shared__ __align__(16) float sm[];   // NSTAGE * STAGE_FLOATS
    __shared__ int   sTok[TILE_M];
    __shared__ float sW[TILE_M];
    __shared__ float sBias[TILE_N];

    const int tid  = threadIdx.x;
    const int lane = tid & 31, w = tid >> 5;
    const int wm = w & 3, wn = w >> 2;          // 4(M) x 2(N); warp tile 32 x 72
    const int g  = lane >> 2, tg = lane & 3;

    const int e  = g_tile_e[mt];
    const int r0 = g_tile_r0[mt];
    const float* WeE = g_We + (size_t)e*Oo*Dd;

    if (tid < TILE_M) { sTok[tid] = g_rows[r0 + tid]; sW[tid] = g_roww[r0 + tid]; }
    if (tid < TILE_N) sBias[tid] = be[e*Oo + o0 + tid];
    __syncthreads();

    // --- stage loader ---
    auto load_stage = [&](int kc, int st) {
        float* As = sm + st*STAGE_FLOATS;
        float* Bs = As + TILE_M*SA;
        const int kb = kc*32;
#pragma unroll
        for (int j = 0; j < 4; j++) {             // A: 128x32 = 1024 x 16B
            int q = tid + j*256;
            int r = q >> 3, fc = (q & 7)*4;
            int tk = sTok[r];
            const float* src = (tk >= 0) ? (g_XT + (size_t)(tk >> 1)*Dd + kb + fc) : g_XT;
            cp16(As + r*SA + fc, src, tk >= 0);
        }
#pragma unroll
        for (int j = 0; j < 5; j++) {             // B: 144x32 = 1152 x 16B
            int q = tid + j*256;
            if (q < TILE_N*8) {
                int r = q >> 3, fc = (q & 7)*4;
                cp16(Bs + r*SA + fc, WeE + (size_t)(o0 + r)*Dd + kb + fc, true);
            }
        }
    };

    float acc[2][9][4];
#pragma unroll
    for (int mf = 0; mf < 2; mf++)
#pragma unroll
        for (int nf = 0; nf < 9; nf++)
#pragma unroll
            for (int i = 0; i < 4; i++) acc[mf][nf][i] = 0.f;

    load_stage(0, 0);
    asm volatile("cp.async.commit_group;\n");
    load_stage(1, 1);
    asm volatile("cp.async.commit_group;\n");

    for (int kc = 0; kc < NKCHUNK; kc++) {
        const int st = kc % NSTAGE;
        asm volatile("cp.async.wait_group 1;\n");
        __syncthreads();                          // all warps done with buffer (kc+2)%3 too

        if (kc + 2 < NKCHUNK) load_stage(kc + 2, (kc + 2) % NSTAGE);
        asm volatile("cp.async.commit_group;\n");

        const float* As = sm + st*STAGE_FLOATS;
        const float* Bs = As + TILE_M*SA;

#pragma unroll
        for (int ks = 0; ks < 4; ks++) {
            const int k0 = ks*8;
            uint32_t a[2][4], bf[9][2];
#pragma unroll
            for (int mf = 0; mf < 2; mf++) {
                int rb = wm*32 + mf*16;
                a[mf][0] = __float_as_uint(As[(rb +     g)*SA + k0 +     tg]);
                a[mf][1] = __float_as_uint(As[(rb + 8 + g)*SA + k0 +     tg]);
                a[mf][2] = __float_as_uint(As[(rb +     g)*SA + k0 + 4 + tg]);
                a[mf][3] = __float_as_uint(As[(rb + 8 + g)*SA + k0 + 4 + tg]);
            }
#pragma unroll
            for (int nf = 0; nf < 9; nf++) {
                int nb = wn*72 + nf*8;
                bf[nf][0] = __float_as_uint(Bs[(nb + g)*SA + k0 +     tg]);
                bf[nf][1] = __float_as_uint(Bs[(nb + g)*SA + k0 + 4 + tg]);
            }
#pragma unroll
            for (int mf = 0; mf < 2; mf++)
#pragma unroll
                for (int nf = 0; nf < 9; nf++) {
                    float* c = acc[mf][nf];
                    asm volatile(
                        "mma.sync.aligned.m16n8k8.row.col.f32.tf32.tf32.f32 "
                        "{%0,%1,%2,%3}, {%4,%5,%6,%7}, {%8,%9}, {%0,%1,%2,%3};\n"
                        : "+f"(c[0]), "+f"(c[1]), "+f"(c[2]), "+f"(c[3])
                        : "r"(a[mf][0]), "r"(a[mf][1]), "r"(a[mf][2]), "r"(a[mf][3]),
                          "r"(bf[nf][0]), "r"(bf[nf][1]));
                }
        }
    }

    // epilogue: out = coef * (acc + bias) into slot-partial buffers (deterministic)
#pragma unroll
    for (int mf = 0; mf < 2; mf++) {
#pragma unroll
        for (int nf = 0; nf < 9; nf++) {
            int c = wn*72 + nf*8 + tg*2;
            int o = o0 + c;
#pragma unroll
            for (int h = 0; h < 2; h++) {
                int r = wm*32 + mf*16 + g + h*8;
                int tk = sTok[r];
                if (tk < 0) continue;
                float wv = sW[r];
                float2 v;
                v.x = wv * (acc[mf][nf][h*2 + 0] + sBias[c]);
                v.y = wv * (acc[mf][nf][h*2 + 1] + sBias[c + 1]);
                *(float2*)(&g_part[tk & 1][(size_t)(tk >> 1)*Oo + o]) = v;
            }
        }
    }
}

// ---------------- K5: sum slot partials + transpose [B,V,O] -> [B,O,V] ----------------
__global__ void k5_out(float* __restrict__ out) {
    __shared__ float s[32][33];
    const int b = blockIdx.z, v0 = blockIdx.x*32, o0 = blockIdx.y*32;
    const int tx = threadIdx.x, ty = threadIdx.y;
#pragma unroll
    for (int i = 0; i < 4; i++) {
        int vy = ty + i*8;
        int o = o0 + tx;
        if (o < Oo) {
            size_t idx = (size_t)(b*Vv + v0 + vy)*Oo + o;
            s[vy][tx] = g_part[0][idx] + g_part[1][idx];
        }
    }
    __syncthreads();
#pragma unroll
    for (int i = 0; i < 4; i++) {
        int oy = ty + i*8;
        if (o0 + oy < Oo)
            out[((size_t)b*Oo + o0 + oy)*Vv + v0 + tx] = s[tx][oy];
    }
}

// ---------------- launch ----------------
extern "C" void kernel_launch(void* const* d_in, const int* in_sizes, int n_in,
                              void* d_out, int out_size) {
    const float* x  = (const float*)d_in[0];
    const float* Wg = (const float*)d_in[1];
    const float* We = (const float*)d_in[2];
    const float* be = (const float*)d_in[3];
    float* out = (float*)d_out;

    static int smem_set = 0;
    const int k4_smem = NSTAGE * STAGE_FLOATS * 4;   // 117504 B
    if (!smem_set) {
        cudaFuncSetAttribute(k4_gemm, cudaFuncAttributeMaxDynamicSharedMemorySize, k4_smem);
        smem_set = 1;
    }

    k0_prep<<<(Ee*Oo*Dd + 1023)/1024, 1024>>>(We);
    k1_gate<<<dim3(Vv/128, Bb), 128>>>(x, Wg);
    k2_plan<<<1, 32>>>();
    k3_scatter<<<(NTOK + 255)/256, 256>>>();
    k4_gemm<<<dim3(5, MAX_TILES), 256, k4_smem>>>(be);
    k5_out<<<dim3(Vv/32, (Oo + 31)/32, Bb), dim3(32, 8)>>>(out);
}

// round 4
// speedup vs baseline: 1.5651x; 1.0272x over previous
#include <cuda_runtime.h>
#include <cuda_bf16.h>
#include <math.h>
#include <stdint.h>

// Problem constants
#define Bb   64
#define Dd   512
#define Vv   512
#define Oo   720
#define Ee   8
#define NTOK    (Bb*Vv)        // 32768 tokens
#define NASSIGN (NTOK*2)       // 65536 assignments (top_k = 2)
#define TILE_M  128
#define TILE_N  144            // 720 = 5 * 144
#define MAX_TILES (NASSIGN/TILE_M + Ee)   // 520
#define ROWS_CAP  (MAX_TILES*TILE_M)
#define SA 36                  // smem row stride (floats)
#define STAGE_FLOATS ((TILE_M + TILE_N) * SA)   // 9792 floats
#define NSTAGE 3
#define NKCHUNK (Dd/32)        // 16

// ---------------- static device scratch ----------------
__device__ float g_XT[NTOK*Dd];          // tokens [B*V][D], tf32-rounded (RNA)
__device__ float g_part[2][NTOK*Oo];     // per-slot partial outputs
__device__ int   g_rows[ROWS_CAP];
__device__ float g_roww[ROWS_CAP];
__device__ int   g_counts[Ee];           // zero-initialized at load; k2 re-zeros each call
__device__ int   g_cursor[Ee];
__device__ int   g_tile_e[MAX_TILES];
__device__ int   g_tile_r0[MAX_TILES];
__device__ int   g_ntiles;
__device__ int   g_sel[NASSIGN];
__device__ float g_wsel[NASSIGN];

__device__ __forceinline__ float to_tf32(float x) {
    float r; asm("cvt.rna.tf32.f32 %0, %1;" : "=f"(r) : "f"(x)); return r;
}
__device__ __forceinline__ void cp16(float* smem_ptr, const float* gptr, bool valid) {
    uint32_t saddr = (uint32_t)__cvta_generic_to_shared(smem_ptr);
    int sz = valid ? 16 : 0;
    asm volatile("cp.async.cg.shared.global [%0], [%1], 16, %2;\n"
                 :: "r"(saddr), "l"(gptr), "r"(sz));
}

// ---------------- K1: fused transpose + gating + softmax + top-2 ----------------
__global__ void k1_gate(const float* __restrict__ x, const float* __restrict__ Wg) {
    __shared__ float sWg[Ee*Dd];
    __shared__ float sX[32][129];
    const int b  = blockIdx.y;
    const int v0 = blockIdx.x * 128;
    const int tid = threadIdx.x;
    const int wq = tid >> 5, lane = tid & 31;

    for (int i = tid; i < Ee*Dd; i += 128) sWg[i] = Wg[i];
    __syncthreads();

    float lg[Ee];
#pragma unroll
    for (int e = 0; e < Ee; e++) lg[e] = 0.f;

    for (int dc = 0; dc < Dd/32; dc++) {
#pragma unroll
        for (int i = 0; i < 32; i++)
            sX[i][tid] = x[((size_t)b*Dd + dc*32 + i)*Vv + v0 + tid];
        __syncthreads();
#pragma unroll
        for (int i = 0; i < 32; i++) {
            float xv = sX[i][tid];
            int d = dc*32 + i;
#pragma unroll
            for (int e = 0; e < Ee; e++) lg[e] += xv * sWg[e*Dd + d];
        }
#pragma unroll
        for (int r = 0; r < 32; r++) {
            int v = wq*32 + r;
            g_XT[((size_t)(b*Vv + v0 + v))*Dd + dc*32 + lane] = to_tf32(sX[lane][v]);
        }
        __syncthreads();
    }

    float m = lg[0];
#pragma unroll
    for (int e = 1; e < Ee; e++) m = fmaxf(m, lg[e]);
    float p[Ee], s = 0.f;
#pragma unroll
    for (int e = 0; e < Ee; e++) { p[e] = expf(lg[e] - m); s += p[e]; }
    float inv = 1.f / s;
#pragma unroll
    for (int e = 0; e < Ee; e++) p[e] *= inv;

    int i1 = 0;
#pragma unroll
    for (int e = 1; e < Ee; e++) if (p[e] > p[i1]) i1 = e;
    int i2 = (i1 == 0) ? 1 : 0;
#pragma unroll
    for (int e = 0; e < Ee; e++) if (e != i1 && p[e] > p[i2]) i2 = e;

    int t = b*Vv + v0 + tid;
    g_sel[2*t + 0] = i1;  g_wsel[2*t + 0] = p[i1];
    g_sel[2*t + 1] = i2;  g_wsel[2*t + 1] = p[i2];
    atomicAdd(&g_counts[i1], 1);
    atomicAdd(&g_counts[i2], 1);
}

// ---------------- K2: plan tiles; re-zero counters for next call ----------------
__global__ void k2_plan() {
    if (threadIdx.x != 0 || blockIdx.x != 0) return;
    int base = 0, nt = 0;
    for (int e = 0; e < Ee; e++) {
        int cnt = g_counts[e];
        g_counts[e] = 0;                   // consumed; ready for next call's k1
        g_cursor[e] = base;
        int t = (cnt + TILE_M - 1) / TILE_M;
        for (int i = 0; i < t; i++) { g_tile_e[nt] = e; g_tile_r0[nt] = base + i*TILE_M; nt++; }
        for (int pq = base + cnt; pq < base + t*TILE_M; pq++) g_rows[pq] = -1;
        base += t*TILE_M;
    }
    g_ntiles = nt;
}

// ---------------- K3: block-aggregated scatter ----------------
__global__ void k3_scatter() {
    __shared__ int hcnt[Ee];
    __shared__ int hbase[Ee];
    const int tid = threadIdx.x;
    const int t = blockIdx.x * blockDim.x + tid;
    if (tid < Ee) hcnt[tid] = 0;
    __syncthreads();
    int e1 = 0, e2 = 0, p1 = 0, p2 = 0;
    float w1 = 0.f, w2 = 0.f;
    if (t < NTOK) {
        e1 = g_sel[2*t + 0];  w1 = g_wsel[2*t + 0];
        e2 = g_sel[2*t + 1];  w2 = g_wsel[2*t + 1];
        p1 = atomicAdd(&hcnt[e1], 1);
        p2 = atomicAdd(&hcnt[e2], 1);
    }
    __syncthreads();
    if (tid < Ee) hbase[tid] = atomicAdd(&g_cursor[tid], hcnt[tid]);
    __syncthreads();
    if (t < NTOK) {
        int q1 = hbase[e1] + p1;
        int q2 = hbase[e2] + p2;
        g_rows[q1] = 2*t + 0;  g_roww[q1] = w1;
        g_rows[q2] = 2*t + 1;  g_roww[q2] = w2;
    }
}

// ---------------- K4: grouped GEMM, tf32 mma.sync, pipelined fragments ----------------
// grid (5, MAX_TILES); B read straight from We (HW tf32 truncation).
__global__ __launch_bounds__(256) void k4_gemm(const float* __restrict__ We,
                                               const float* __restrict__ be) {
    const int mt = blockIdx.y;
    if (mt >= g_ntiles) return;
    const int o0 = blockIdx.x * TILE_N;

    extern __shared__ __align__(16) float sm[];   // NSTAGE * STAGE_FLOATS
    __shared__ int   sTok[TILE_M];
    __shared__ float sW[TILE_M];
    __shared__ float sBias[TILE_N];

    const int tid  = threadIdx.x;
    const int lane = tid & 31, w = tid >> 5;
    const int wm = w & 3, wn = w >> 2;          // 4(M) x 2(N); warp tile 32 x 72
    const int g  = lane >> 2, tg = lane & 3;

    const int e  = g_tile_e[mt];
    const int r0 = g_tile_r0[mt];
    const float* WeE = We + (size_t)e*Oo*Dd;

    if (tid < TILE_M) { sTok[tid] = g_rows[r0 + tid]; sW[tid] = g_roww[r0 + tid]; }
    if (tid < TILE_N) sBias[tid] = be[e*Oo + o0 + tid];
    __syncthreads();

    auto load_stage = [&](int kc, int st) {
        float* As = sm + st*STAGE_FLOATS;
        float* Bs = As + TILE_M*SA;
        const int kb = kc*32;
#pragma unroll
        for (int j = 0; j < 4; j++) {             // A: 128x32
            int q = tid + j*256;
            int r = q >> 3, fc = (q & 7)*4;
            int tk = sTok[r];
            const float* src = (tk >= 0) ? (g_XT + (size_t)(tk >> 1)*Dd + kb + fc) : g_XT;
            cp16(As + r*SA + fc, src, tk >= 0);
        }
#pragma unroll
        for (int j = 0; j < 5; j++) {             // B: 144x32
            int q = tid + j*256;
            if (q < TILE_N*8) {
                int r = q >> 3, fc = (q & 7)*4;
                cp16(Bs + r*SA + fc, WeE + (size_t)(o0 + r)*Dd + kb + fc, true);
            }
        }
    };

    float acc[2][9][4];
#pragma unroll
    for (int mf = 0; mf < 2; mf++)
#pragma unroll
        for (int nf = 0; nf < 9; nf++)
#pragma unroll
            for (int i = 0; i < 4; i++) acc[mf][nf][i] = 0.f;

    load_stage(0, 0);
    asm volatile("cp.async.commit_group;\n");
    load_stage(1, 1);
    asm volatile("cp.async.commit_group;\n");

    uint32_t a[2][2][4], bf[2][9][2];             // double-buffered fragments

    auto load_frags = [&](const float* As, const float* Bs, int ks, int buf) {
        const int k0 = ks*8;
#pragma unroll
        for (int mf = 0; mf < 2; mf++) {
            int rb = wm*32 + mf*16;
            a[buf][mf][0] = __float_as_uint(As[(rb +     g)*SA + k0 +     tg]);
            a[buf][mf][1] = __float_as_uint(As[(rb + 8 + g)*SA + k0 +     tg]);
            a[buf][mf][2] = __float_as_uint(As[(rb +     g)*SA + k0 + 4 + tg]);
            a[buf][mf][3] = __float_as_uint(As[(rb + 8 + g)*SA + k0 + 4 + tg]);
        }
#pragma unroll
        for (int nf = 0; nf < 9; nf++) {
            int nb = wn*72 + nf*8;
            bf[buf][nf][0] = __float_as_uint(Bs[(nb + g)*SA + k0 +     tg]);
            bf[buf][nf][1] = __float_as_uint(Bs[(nb + g)*SA + k0 + 4 + tg]);
        }
    };

    auto issue_mma = [&](int buf) {
#pragma unroll
        for (int mf = 0; mf < 2; mf++)
#pragma unroll
            for (int nf = 0; nf < 9; nf++) {
                float* c = acc[mf][nf];
                asm volatile(
                    "mma.sync.aligned.m16n8k8.row.col.f32.tf32.tf32.f32 "
                    "{%0,%1,%2,%3}, {%4,%5,%6,%7}, {%8,%9}, {%0,%1,%2,%3};\n"
                    : "+f"(c[0]), "+f"(c[1]), "+f"(c[2]), "+f"(c[3])
                    : "r"(a[buf][mf][0]), "r"(a[buf][mf][1]), "r"(a[buf][mf][2]), "r"(a[buf][mf][3]),
                      "r"(bf[buf][nf][0]), "r"(bf[buf][nf][1]));
            }
    };

    for (int kc = 0; kc < NKCHUNK; kc++) {
        const int st = kc % NSTAGE;
        asm volatile("cp.async.wait_group 1;\n");
        __syncthreads();

        if (kc + 2 < NKCHUNK) load_stage(kc + 2, (kc + 2) % NSTAGE);
        asm volatile("cp.async.commit_group;\n");

        const float* As = sm + st*STAGE_FLOATS;
        const float* Bs = As + TILE_M*SA;

        load_frags(As, Bs, 0, 0);
#pragma unroll
        for (int ks = 0; ks < 4; ks++) {
            if (ks < 3) load_frags(As, Bs, ks + 1, (ks + 1) & 1);
            issue_mma(ks & 1);
        }
    }

    // epilogue: out = coef * (acc + bias) into slot-partial buffers (deterministic)
#pragma unroll
    for (int mf = 0; mf < 2; mf++) {
#pragma unroll
        for (int nf = 0; nf < 9; nf++) {
            int c = wn*72 + nf*8 + tg*2;
            int o = o0 + c;
#pragma unroll
            for (int h = 0; h < 2; h++) {
                int r = wm*32 + mf*16 + g + h*8;
                int tk = sTok[r];
                if (tk < 0) continue;
                float wv = sW[r];
                float2 v;
                v.x = wv * (acc[mf][nf][h*2 + 0] + sBias[c]);
                v.y = wv * (acc[mf][nf][h*2 + 1] + sBias[c + 1]);
                *(float2*)(&g_part[tk & 1][(size_t)(tk >> 1)*Oo + o]) = v;
            }
        }
    }
}

// ---------------- K5: sum slot partials + transpose [B,V,O] -> [B,O,V] ----------------
__global__ void k5_out(float* __restrict__ out) {
    __shared__ float s[32][33];
    const int b = blockIdx.z, v0 = blockIdx.x*32, o0 = blockIdx.y*32;
    const int tx = threadIdx.x, ty = threadIdx.y;
#pragma unroll
    for (int i = 0; i < 4; i++) {
        int vy = ty + i*8;
        int o = o0 + tx;
        if (o < Oo) {
            size_t idx = (size_t)(b*Vv + v0 + vy)*Oo + o;
            s[vy][tx] = g_part[0][idx] + g_part[1][idx];
        }
    }
    __syncthreads();
#pragma unroll
    for (int i = 0; i < 4; i++) {
        int oy = ty + i*8;
        if (o0 + oy < Oo)
            out[((size_t)b*Oo + o0 + oy)*Vv + v0 + tx] = s[tx][oy];
    }
}

// ---------------- launch ----------------
extern "C" void kernel_launch(void* const* d_in, const int* in_sizes, int n_in,
                              void* d_out, int out_size) {
    const float* x  = (const float*)d_in[0];
    const float* Wg = (const float*)d_in[1];
    const float* We = (const float*)d_in[2];
    const float* be = (const float*)d_in[3];
    float* out = (float*)d_out;

    static int smem_set = 0;
    const int k4_smem = NSTAGE * STAGE_FLOATS * 4;   // 117504 B
    if (!smem_set) {
        cudaFuncSetAttribute(k4_gemm, cudaFuncAttributeMaxDynamicSharedMemorySize, k4_smem);
        smem_set = 1;
    }

    k1_gate<<<dim3(Vv/128, Bb), 128>>>(x, Wg);
    k2_plan<<<1, 32>>>();
    k3_scatter<<<(NTOK + 255)/256, 256>>>();
    k4_gemm<<<dim3(5, MAX_TILES), 256, k4_smem>>>(We, be);
    k5_out<<<dim3(Vv/32, (Oo + 31)/32, Bb), dim3(32, 8)>>>(out);
}

// round 5
// speedup vs baseline: 1.8325x; 1.1708x over previous
#include <cuda_runtime.h>
#include <cuda_bf16.h>
#include <math.h>
#include <stdint.h>

// Problem constants
#define Bb   64
#define Dd   512
#define Vv   512
#define Oo   720
#define Ee   8
#define NTOK    (Bb*Vv)        // 32768 tokens
#define NASSIGN (NTOK*2)       // 65536 assignments (top_k = 2)
#define TILE_M  128
#define TILE_N  144            // 720 = 5 * 144
#define MAX_TILES (NASSIGN/TILE_M + Ee)   // 520
#define ROWS_CAP  (MAX_TILES*TILE_M)
#define SA 36                  // smem row stride (floats)
#define STAGE_FLOATS ((TILE_M + TILE_N) * SA)   // 9792 floats = 39168 B
#define NSTAGE 2
#define NKCHUNK (Dd/32)        // 16

// ---------------- static device scratch ----------------
__device__ float g_XT[NTOK*Dd];          // tokens [B*V][D], tf32-rounded (RNA)
__device__ float g_part[2][NTOK*Oo];     // per-slot partial outputs
__device__ int   g_rows[ROWS_CAP];
__device__ float g_roww[ROWS_CAP];
__device__ int   g_counts[Ee];           // zero-initialized; k2 re-zeros each call
__device__ int   g_cursor[Ee];
__device__ int   g_tile_e[MAX_TILES];
__device__ int   g_tile_r0[MAX_TILES];
__device__ int   g_ntiles;
__device__ int   g_sel[NASSIGN];
__device__ float g_wsel[NASSIGN];

__device__ __forceinline__ float to_tf32(float x) {
    float r; asm("cvt.rna.tf32.f32 %0, %1;" : "=f"(r) : "f"(x)); return r;
}
__device__ __forceinline__ void cp16(float* smem_ptr, const float* gptr, bool valid) {
    uint32_t saddr = (uint32_t)__cvta_generic_to_shared(smem_ptr);
    int sz = valid ? 16 : 0;
    asm volatile("cp.async.cg.shared.global [%0], [%1], 16, %2;\n"
                 :: "r"(saddr), "l"(gptr), "r"(sz));
}

// ---------------- K1: fused transpose + gating + softmax + top-2 ----------------
__global__ void k1_gate(const float* __restrict__ x, const float* __restrict__ Wg) {
    __shared__ float sWg[Ee*Dd];
    __shared__ float sX[32][129];
    const int b  = blockIdx.y;
    const int v0 = blockIdx.x * 128;
    const int tid = threadIdx.x;
    const int wq = tid >> 5, lane = tid & 31;

    for (int i = tid; i < Ee*Dd; i += 128) sWg[i] = Wg[i];
    __syncthreads();

    float lg[Ee];
#pragma unroll
    for (int e = 0; e < Ee; e++) lg[e] = 0.f;

    for (int dc = 0; dc < Dd/32; dc++) {
#pragma unroll
        for (int i = 0; i < 32; i++)
            sX[i][tid] = x[((size_t)b*Dd + dc*32 + i)*Vv + v0 + tid];
        __syncthreads();
#pragma unroll
        for (int i = 0; i < 32; i++) {
            float xv = sX[i][tid];
            int d = dc*32 + i;
#pragma unroll
            for (int e = 0; e < Ee; e++) lg[e] += xv * sWg[e*Dd + d];
        }
#pragma unroll
        for (int r = 0; r < 32; r++) {
            int v = wq*32 + r;
            g_XT[((size_t)(b*Vv + v0 + v))*Dd + dc*32 + lane] = to_tf32(sX[lane][v]);
        }
        __syncthreads();
    }

    float m = lg[0];
#pragma unroll
    for (int e = 1; e < Ee; e++) m = fmaxf(m, lg[e]);
    float p[Ee], s = 0.f;
#pragma unroll
    for (int e = 0; e < Ee; e++) { p[e] = expf(lg[e] - m); s += p[e]; }
    float inv = 1.f / s;
#pragma unroll
    for (int e = 0; e < Ee; e++) p[e] *= inv;

    int i1 = 0;
#pragma unroll
    for (int e = 1; e < Ee; e++) if (p[e] > p[i1]) i1 = e;
    int i2 = (i1 == 0) ? 1 : 0;
#pragma unroll
    for (int e = 0; e < Ee; e++) if (e != i1 && p[e] > p[i2]) i2 = e;

    int t = b*Vv + v0 + tid;
    g_sel[2*t + 0] = i1;  g_wsel[2*t + 0] = p[i1];
    g_sel[2*t + 1] = i2;  g_wsel[2*t + 1] = p[i2];
    atomicAdd(&g_counts[i1], 1);
    atomicAdd(&g_counts[i2], 1);
}

// ---------------- K2: plan tiles; re-zero counters ----------------
__global__ void k2_plan() {
    if (threadIdx.x != 0 || blockIdx.x != 0) return;
    int base = 0, nt = 0;
    for (int e = 0; e < Ee; e++) {
        int cnt = g_counts[e];
        g_counts[e] = 0;
        g_cursor[e] = base;
        int t = (cnt + TILE_M - 1) / TILE_M;
        for (int i = 0; i < t; i++) { g_tile_e[nt] = e; g_tile_r0[nt] = base + i*TILE_M; nt++; }
        for (int pq = base + cnt; pq < base + t*TILE_M; pq++) g_rows[pq] = -1;
        base += t*TILE_M;
    }
    g_ntiles = nt;
}

// ---------------- K3: block-aggregated scatter ----------------
__global__ void k3_scatter() {
    __shared__ int hcnt[Ee];
    __shared__ int hbase[Ee];
    const int tid = threadIdx.x;
    const int t = blockIdx.x * blockDim.x + tid;
    if (tid < Ee) hcnt[tid] = 0;
    __syncthreads();
    int e1 = 0, e2 = 0, p1 = 0, p2 = 0;
    float w1 = 0.f, w2 = 0.f;
    if (t < NTOK) {
        e1 = g_sel[2*t + 0];  w1 = g_wsel[2*t + 0];
        e2 = g_sel[2*t + 1];  w2 = g_wsel[2*t + 1];
        p1 = atomicAdd(&hcnt[e1], 1);
        p2 = atomicAdd(&hcnt[e2], 1);
    }
    __syncthreads();
    if (tid < Ee) hbase[tid] = atomicAdd(&g_cursor[tid], hcnt[tid]);
    __syncthreads();
    if (t < NTOK) {
        int q1 = hbase[e1] + p1;
        int q2 = hbase[e2] + p2;
        g_rows[q1] = 2*t + 0;  g_roww[q1] = w1;
        g_rows[q2] = 2*t + 1;  g_roww[q2] = w2;
    }
}

// ---------------- K4: grouped GEMM, tf32 mma.sync, 2-stage, 2 CTAs/SM ----------------
__global__ __launch_bounds__(256, 2) void k4_gemm(const float* __restrict__ We,
                                                  const float* __restrict__ be) {
    const int mt = blockIdx.y;
    if (mt >= g_ntiles) return;
    const int o0 = blockIdx.x * TILE_N;

    extern __shared__ __align__(16) float sm[];   // NSTAGE * STAGE_FLOATS
    __shared__ int   sTok[TILE_M];
    __shared__ float sW[TILE_M];
    __shared__ float sBias[TILE_N];

    const int tid  = threadIdx.x;
    const int lane = tid & 31, w = tid >> 5;
    const int wm = w & 3, wn = w >> 2;          // 4(M) x 2(N); warp tile 32 x 72
    const int g  = lane >> 2, tg = lane & 3;

    const int e  = g_tile_e[mt];
    const int r0 = g_tile_r0[mt];
    const float* WeE = We + (size_t)e*Oo*Dd;

    if (tid < TILE_M) { sTok[tid] = g_rows[r0 + tid]; sW[tid] = g_roww[r0 + tid]; }
    if (tid < TILE_N) sBias[tid] = be[e*Oo + o0 + tid];
    __syncthreads();

    auto load_stage = [&](int kc, int st) {
        float* As = sm + st*STAGE_FLOATS;
        float* Bs = As + TILE_M*SA;
        const int kb = kc*32;
#pragma unroll
        for (int j = 0; j < 4; j++) {             // A: 128x32
            int q = tid + j*256;
            int r = q >> 3, fc = (q & 7)*4;
            int tk = sTok[r];
            const float* src = (tk >= 0) ? (g_XT + (size_t)(tk >> 1)*Dd + kb + fc) : g_XT;
            cp16(As + r*SA + fc, src, tk >= 0);
        }
#pragma unroll
        for (int j = 0; j < 5; j++) {             // B: 144x32
            int q = tid + j*256;
            if (q < TILE_N*8) {
                int r = q >> 3, fc = (q & 7)*4;
                cp16(Bs + r*SA + fc, WeE + (size_t)(o0 + r)*Dd + kb + fc, true);
            }
        }
    };

    float acc[2][9][4];
#pragma unroll
    for (int mf = 0; mf < 2; mf++)
#pragma unroll
        for (int nf = 0; nf < 9; nf++)
#pragma unroll
            for (int i = 0; i < 4; i++) acc[mf][nf][i] = 0.f;

    load_stage(0, 0);
    asm volatile("cp.async.commit_group;\n");

    for (int kc = 0; kc < NKCHUNK; kc++) {
        const int st = kc & 1;
        asm volatile("cp.async.wait_group 0;\n");
        __syncthreads();                          // data ready; all warps off other buffer

        if (kc + 1 < NKCHUNK) load_stage(kc + 1, st ^ 1);
        asm volatile("cp.async.commit_group;\n");

        const float* As = sm + st*STAGE_FLOATS;
        const float* Bs = As + TILE_M*SA;

#pragma unroll
        for (int ks = 0; ks < 4; ks++) {
            const int k0 = ks*8;
            uint32_t a[2][4], bf[9][2];
#pragma unroll
            for (int mf = 0; mf < 2; mf++) {
                int rb = wm*32 + mf*16;
                a[mf][0] = __float_as_uint(As[(rb +     g)*SA + k0 +     tg]);
                a[mf][1] = __float_as_uint(As[(rb + 8 + g)*SA + k0 +     tg]);
                a[mf][2] = __float_as_uint(As[(rb +     g)*SA + k0 + 4 + tg]);
                a[mf][3] = __float_as_uint(As[(rb + 8 + g)*SA + k0 + 4 + tg]);
            }
#pragma unroll
            for (int nf = 0; nf < 9; nf++) {
                int nb = wn*72 + nf*8;
                bf[nf][0] = __float_as_uint(Bs[(nb + g)*SA + k0 +     tg]);
                bf[nf][1] = __float_as_uint(Bs[(nb + g)*SA + k0 + 4 + tg]);
            }
#pragma unroll
            for (int mf = 0; mf < 2; mf++)
#pragma unroll
                for (int nf = 0; nf < 9; nf++) {
                    float* c = acc[mf][nf];
                    asm volatile(
                        "mma.sync.aligned.m16n8k8.row.col.f32.tf32.tf32.f32 "
                        "{%0,%1,%2,%3}, {%4,%5,%6,%7}, {%8,%9}, {%0,%1,%2,%3};\n"
                        : "+f"(c[0]), "+f"(c[1]), "+f"(c[2]), "+f"(c[3])
                        : "r"(a[mf][0]), "r"(a[mf][1]), "r"(a[mf][2]), "r"(a[mf][3]),
                          "r"(bf[nf][0]), "r"(bf[nf][1]));
                }
        }
    }

    // epilogue: out = coef * (acc + bias) into slot-partial buffers (deterministic)
#pragma unroll
    for (int mf = 0; mf < 2; mf++) {
#pragma unroll
        for (int nf = 0; nf < 9; nf++) {
            int c = wn*72 + nf*8 + tg*2;
            int o = o0 + c;
#pragma unroll
            for (int h = 0; h < 2; h++) {
                int r = wm*32 + mf*16 + g + h*8;
                int tk = sTok[r];
                if (tk < 0) continue;
                float wv = sW[r];
                float2 v;
                v.x = wv * (acc[mf][nf][h*2 + 0] + sBias[c]);
                v.y = wv * (acc[mf][nf][h*2 + 1] + sBias[c + 1]);
                *(float2*)(&g_part[tk & 1][(size_t)(tk >> 1)*Oo + o]) = v;
            }
        }
    }
}

// ---------------- K5: sum slot partials + transpose [B,V,O] -> [B,O,V] ----------------
__global__ void k5_out(float* __restrict__ out) {
    __shared__ float s[32][33];
    const int b = blockIdx.z, v0 = blockIdx.x*32, o0 = blockIdx.y*32;
    const int tx = threadIdx.x, ty = threadIdx.y;
#pragma unroll
    for (int i = 0; i < 4; i++) {
        int vy = ty + i*8;
        int o = o0 + tx;
        if (o < Oo) {
            size_t idx = (size_t)(b*Vv + v0 + vy)*Oo + o;
            s[vy][tx] = g_part[0][idx] + g_part[1][idx];
        }
    }
    __syncthreads();
#pragma unroll
    for (int i = 0; i < 4; i++) {
        int oy = ty + i*8;
        if (o0 + oy < Oo)
            out[((size_t)b*Oo + o0 + oy)*Vv + v0 + tx] = s[tx][oy];
    }
}

// ---------------- launch ----------------
extern "C" void kernel_launch(void* const* d_in, const int* in_sizes, int n_in,
                              void* d_out, int out_size) {
    const float* x  = (const float*)d_in[0];
    const float* Wg = (const float*)d_in[1];
    const float* We = (const float*)d_in[2];
    const float* be = (const float*)d_in[3];
    float* out = (float*)d_out;

    static int smem_set = 0;
    const int k4_smem = NSTAGE * STAGE_FLOATS * 4;   // 78336 B
    if (!smem_set) {
        cudaFuncSetAttribute(k4_gemm, cudaFuncAttributeMaxDynamicSharedMemorySize, k4_smem);
        smem_set = 1;
    }

    k1_gate<<<dim3(Vv/128, Bb), 128>>>(x, Wg);
    k2_plan<<<1, 32>>>();
    k3_scatter<<<(NTOK + 255)/256, 256>>>();
    k4_gemm<<<dim3(5, MAX_TILES), 256, k4_smem>>>(We, be);
    k5_out<<<dim3(Vv/32, (Oo + 31)/32, Bb), dim3(32, 8)>>>(out);
}

// round 6
// speedup vs baseline: 1.9421x; 1.0598x over previous
#include <cuda_runtime.h>
#include <cuda_bf16.h>
#include <math.h>
#include <stdint.h>

// Problem constants
#define Bb   64
#define Dd   512
#define Vv   512
#define Oo   720
#define Ee   8
#define NTOK    (Bb*Vv)        // 32768 tokens
#define NASSIGN (NTOK*2)       // 65536 assignments (top_k = 2)
#define TILE_M  128
#define TILE_N  144            // 720 = 5 * 144
#define MAX_TILES (NASSIGN/TILE_M + Ee)   // 520
#define ROWS_CAP  (MAX_TILES*TILE_M)
#define SA 36                  // smem row stride (floats)
#define STAGE_FLOATS ((TILE_M + TILE_N) * SA)   // 9792 floats = 39168 B
#define NSTAGE 2
#define NKCHUNK (Dd/32)        // 16

// ---------------- static device scratch ----------------
__device__ float g_XT[NTOK*Dd];          // tokens [B*V][D], tf32-rounded (RNA)
__device__ float g_part[2][NTOK*Oo];     // per-slot partial outputs
__device__ int   g_rows[ROWS_CAP];
__device__ float g_roww[ROWS_CAP];
__device__ int   g_counts[Ee];           // zero-initialized; k2 re-zeros each call
__device__ int   g_cursor[Ee];
__device__ int   g_tile_e[MAX_TILES];
__device__ int   g_tile_r0[MAX_TILES];
__device__ int   g_ntiles;
__device__ int   g_sel[NASSIGN];
__device__ float g_wsel[NASSIGN];

__device__ __forceinline__ float to_tf32(float x) {
    float r; asm("cvt.rna.tf32.f32 %0, %1;" : "=f"(r) : "f"(x)); return r;
}
__device__ __forceinline__ void cp16(float* smem_ptr, const float* gptr, bool valid) {
    uint32_t saddr = (uint32_t)__cvta_generic_to_shared(smem_ptr);
    int sz = valid ? 16 : 0;
    asm volatile("cp.async.cg.shared.global [%0], [%1], 16, %2;\n"
                 :: "r"(saddr), "l"(gptr), "r"(sz));
}
__device__ __forceinline__ void ldsm4(uint32_t& r0, uint32_t& r1, uint32_t& r2, uint32_t& r3,
                                      uint32_t addr) {
    asm volatile("ldmatrix.sync.aligned.m8n8.x4.shared.b16 {%0,%1,%2,%3}, [%4];"
                 : "=r"(r0), "=r"(r1), "=r"(r2), "=r"(r3) : "r"(addr));
}
__device__ __forceinline__ void ldsm2(uint32_t& r0, uint32_t& r1, uint32_t addr) {
    asm volatile("ldmatrix.sync.aligned.m8n8.x2.shared.b16 {%0,%1}, [%2];"
                 : "=r"(r0), "=r"(r1) : "r"(addr));
}

// ---------------- K1: fused transpose + gating + softmax + top-2 ----------------
__global__ void k1_gate(const float* __restrict__ x, const float* __restrict__ Wg) {
    __shared__ float sWg[Ee*Dd];
    __shared__ float sX[32][129];
    const int b  = blockIdx.y;
    const int v0 = blockIdx.x * 128;
    const int tid = threadIdx.x;
    const int wq = tid >> 5, lane = tid & 31;

    for (int i = tid; i < Ee*Dd; i += 128) sWg[i] = Wg[i];
    __syncthreads();

    float lg[Ee];
#pragma unroll
    for (int e = 0; e < Ee; e++) lg[e] = 0.f;

    for (int dc = 0; dc < Dd/32; dc++) {
#pragma unroll
        for (int i = 0; i < 32; i++)
            sX[i][tid] = x[((size_t)b*Dd + dc*32 + i)*Vv + v0 + tid];
        __syncthreads();
#pragma unroll
        for (int i = 0; i < 32; i++) {
            float xv = sX[i][tid];
            int d = dc*32 + i;
#pragma unroll
            for (int e = 0; e < Ee; e++) lg[e] += xv * sWg[e*Dd + d];
        }
#pragma unroll
        for (int r = 0; r < 32; r++) {
            int v = wq*32 + r;
            g_XT[((size_t)(b*Vv + v0 + v))*Dd + dc*32 + lane] = to_tf32(sX[lane][v]);
        }
        __syncthreads();
    }

    float m = lg[0];
#pragma unroll
    for (int e = 1; e < Ee; e++) m = fmaxf(m, lg[e]);
    float p[Ee], s = 0.f;
#pragma unroll
    for (int e = 0; e < Ee; e++) { p[e] = expf(lg[e] - m); s += p[e]; }
    float inv = 1.f / s;
#pragma unroll
    for (int e = 0; e < Ee; e++) p[e] *= inv;

    int i1 = 0;
#pragma unroll
    for (int e = 1; e < Ee; e++) if (p[e] > p[i1]) i1 = e;
    int i2 = (i1 == 0) ? 1 : 0;
#pragma unroll
    for (int e = 0; e < Ee; e++) if (e != i1 && p[e] > p[i2]) i2 = e;

    int t = b*Vv + v0 + tid;
    g_sel[2*t + 0] = i1;  g_wsel[2*t + 0] = p[i1];
    g_sel[2*t + 1] = i2;  g_wsel[2*t + 1] = p[i2];
    atomicAdd(&g_counts[i1], 1);
    atomicAdd(&g_counts[i2], 1);
}

// ---------------- K2: plan tiles; re-zero counters ----------------
__global__ void k2_plan() {
    if (threadIdx.x != 0 || blockIdx.x != 0) return;
    int base = 0, nt = 0;
    for (int e = 0; e < Ee; e++) {
        int cnt = g_counts[e];
        g_counts[e] = 0;
        g_cursor[e] = base;
        int t = (cnt + TILE_M - 1) / TILE_M;
        for (int i = 0; i < t; i++) { g_tile_e[nt] = e; g_tile_r0[nt] = base + i*TILE_M; nt++; }
        for (int pq = base + cnt; pq < base + t*TILE_M; pq++) g_rows[pq] = -1;
        base += t*TILE_M;
    }
    g_ntiles = nt;
}

// ---------------- K3: block-aggregated scatter ----------------
__global__ void k3_scatter() {
    __shared__ int hcnt[Ee];
    __shared__ int hbase[Ee];
    const int tid = threadIdx.x;
    const int t = blockIdx.x * blockDim.x + tid;
    if (tid < Ee) hcnt[tid] = 0;
    __syncthreads();
    int e1 = 0, e2 = 0, p1 = 0, p2 = 0;
    float w1 = 0.f, w2 = 0.f;
    if (t < NTOK) {
        e1 = g_sel[2*t + 0];  w1 = g_wsel[2*t + 0];
        e2 = g_sel[2*t + 1];  w2 = g_wsel[2*t + 1];
        p1 = atomicAdd(&hcnt[e1], 1);
        p2 = atomicAdd(&hcnt[e2], 1);
    }
    __syncthreads();
    if (tid < Ee) hbase[tid] = atomicAdd(&g_cursor[tid], hcnt[tid]);
    __syncthreads();
    if (t < NTOK) {
        int q1 = hbase[e1] + p1;
        int q2 = hbase[e2] + p2;
        g_rows[q1] = 2*t + 0;  g_roww[q1] = w1;
        g_rows[q2] = 2*t + 1;  g_roww[q2] = w2;
    }
}

// ---------------- K4: grouped GEMM, tf32 mma.sync + ldmatrix, 2 CTAs/SM ----------------
__global__ __launch_bounds__(256, 2) void k4_gemm(const float* __restrict__ We,
                                                  const float* __restrict__ be) {
    const int mt = blockIdx.y;
    if (mt >= g_ntiles) return;
    const int o0 = blockIdx.x * TILE_N;

    extern __shared__ __align__(16) float sm[];   // NSTAGE * STAGE_FLOATS
    __shared__ int   sTok[TILE_M];
    __shared__ float sW[TILE_M];
    __shared__ float sBias[TILE_N];

    const int tid  = threadIdx.x;
    const int lane = tid & 31, w = tid >> 5;
    const int wm = w & 3, wn = w >> 2;          // 4(M) x 2(N); warp tile 32 x 72
    const int g  = lane >> 2, tg = lane & 3;

    const int e  = g_tile_e[mt];
    const int r0 = g_tile_r0[mt];
    const float* WeE = We + (size_t)e*Oo*Dd;

    if (tid < TILE_M) { sTok[tid] = g_rows[r0 + tid]; sW[tid] = g_roww[r0 + tid]; }
    if (tid < TILE_N) sBias[tid] = be[e*Oo + o0 + tid];
    __syncthreads();

    auto load_stage = [&](int kc, int st) {
        float* As = sm + st*STAGE_FLOATS;
        float* Bs = As + TILE_M*SA;
        const int kb = kc*32;
#pragma unroll
        for (int j = 0; j < 4; j++) {             // A: 128x32
            int q = tid + j*256;
            int r = q >> 3, fc = (q & 7)*4;
            int tk = sTok[r];
            const float* src = (tk >= 0) ? (g_XT + (size_t)(tk >> 1)*Dd + kb + fc) : g_XT;
            cp16(As + r*SA + fc, src, tk >= 0);
        }
#pragma unroll
        for (int j = 0; j < 5; j++) {             // B: 144x32
            int q = tid + j*256;
            if (q < TILE_N*8) {
                int r = q >> 3, fc = (q & 7)*4;
                cp16(Bs + r*SA + fc, WeE + (size_t)(o0 + r)*Dd + kb + fc, true);
            }
        }
    };

    // ---- per-lane ldmatrix base addresses (stage 0, k0 = 0), byte units ----
    const uint32_t smA0 = (uint32_t)__cvta_generic_to_shared(sm);
    const uint32_t smB0 = smA0 + TILE_M*SA*4;
    const int rA = lane & 7;                 // row-within-8 for A tiles
    const int aRow = (lane >> 3) & 1;        // +8 rows for tiles 1,3
    const int aCol = (lane >> 4) * 4;        // +4 cols for tiles 2,3
    uint32_t aBase[2];                       // per mf
#pragma unroll
    for (int mf = 0; mf < 2; mf++)
        aBase[mf] = smA0 + (((wm*32 + mf*16 + aRow*8 + rA)*SA) + aCol) * 4;
    const int bRowSel = (lane >> 4) * 8;     // tiles 2,3 -> nf+1 (8 rows down)
    const int bCol = ((lane >> 3) & 1) * 4;  // tiles 1,3 -> +4 cols
    uint32_t bBase[4];                       // per nf-pair p (nf = 2p, 2p+1)
#pragma unroll
    for (int p = 0; p < 4; p++)
        bBase[p] = smB0 + (((wn*72 + p*16 + bRowSel + rA)*SA) + bCol) * 4;
    // x2 for nf=8: lanes 0-15, tiles: [cols k0..3], [cols k0+4..7]
    uint32_t bBase8 = smB0 + (((wn*72 + 64 + rA)*SA) + bCol) * 4;

    float acc[2][9][4];
#pragma unroll
    for (int mf = 0; mf < 2; mf++)
#pragma unroll
        for (int nf = 0; nf < 9; nf++)
#pragma unroll
            for (int i = 0; i < 4; i++) acc[mf][nf][i] = 0.f;

    load_stage(0, 0);
    asm volatile("cp.async.commit_group;\n");

    for (int kc = 0; kc < NKCHUNK; kc++) {
        const int st = kc & 1;
        asm volatile("cp.async.wait_group 0;\n");
        __syncthreads();

        if (kc + 1 < NKCHUNK) load_stage(kc + 1, st ^ 1);
        asm volatile("cp.async.commit_group;\n");

        const uint32_t stOff = (uint32_t)(st*STAGE_FLOATS*4);

#pragma unroll
        for (int ks = 0; ks < 4; ks++) {
            const uint32_t kOff = stOff + ks*8*4;
            uint32_t a[2][4], bf[9][2];
#pragma unroll
            for (int mf = 0; mf < 2; mf++)
                ldsm4(a[mf][0], a[mf][1], a[mf][2], a[mf][3], aBase[mf] + kOff);
#pragma unroll
            for (int p = 0; p < 4; p++)
                ldsm4(bf[2*p][0], bf[2*p][1], bf[2*p+1][0], bf[2*p+1][1], bBase[p] + kOff);
            ldsm2(bf[8][0], bf[8][1], bBase8 + kOff);

#pragma unroll
            for (int mf = 0; mf < 2; mf++)
#pragma unroll
                for (int nf = 0; nf < 9; nf++) {
                    float* c = acc[mf][nf];
                    asm volatile(
                        "mma.sync.aligned.m16n8k8.row.col.f32.tf32.tf32.f32 "
                        "{%0,%1,%2,%3}, {%4,%5,%6,%7}, {%8,%9}, {%0,%1,%2,%3};\n"
                        : "+f"(c[0]), "+f"(c[1]), "+f"(c[2]), "+f"(c[3])
                        : "r"(a[mf][0]), "r"(a[mf][1]), "r"(a[mf][2]), "r"(a[mf][3]),
                          "r"(bf[nf][0]), "r"(bf[nf][1]));
                }
        }
    }

    // epilogue: out = coef * (acc + bias) into slot-partial buffers (deterministic)
#pragma unroll
    for (int mf = 0; mf < 2; mf++) {
#pragma unroll
        for (int nf = 0; nf < 9; nf++) {
            int c = wn*72 + nf*8 + tg*2;
            int o = o0 + c;
#pragma unroll
            for (int h = 0; h < 2; h++) {
                int r = wm*32 + mf*16 + g + h*8;
                int tk = sTok[r];
                if (tk < 0) continue;
                float wv = sW[r];
                float2 v;
                v.x = wv * (acc[mf][nf][h*2 + 0] + sBias[c]);
                v.y = wv * (acc[mf][nf][h*2 + 1] + sBias[c + 1]);
                *(float2*)(&g_part[tk & 1][(size_t)(tk >> 1)*Oo + o]) = v;
            }
        }
    }
}

// ---------------- K5: sum slot partials + transpose [B,V,O] -> [B,O,V] ----------------
__global__ void k5_out(float* __restrict__ out) {
    __shared__ float s[32][33];
    const int b = blockIdx.z, v0 = blockIdx.x*32, o0 = blockIdx.y*32;
    const int tx = threadIdx.x, ty = threadIdx.y;
#pragma unroll
    for (int i = 0; i < 4; i++) {
        int vy = ty + i*8;
        int o = o0 + tx;
        if (o < Oo) {
            size_t idx = (size_t)(b*Vv + v0 + vy)*Oo + o;
            s[vy][tx] = g_part[0][idx] + g_part[1][idx];
        }
    }
    __syncthreads();
#pragma unroll
    for (int i = 0; i < 4; i++) {
        int oy = ty + i*8;
        if (o0 + oy < Oo)
            out[((size_t)b*Oo + o0 + oy)*Vv + v0 + tx] = s[tx][oy];
    }
}

// ---------------- launch ----------------
extern "C" void kernel_launch(void* const* d_in, const int* in_sizes, int n_in,
                              void* d_out, int out_size) {
    const float* x  = (const float*)d_in[0];
    const float* Wg = (const float*)d_in[1];
    const float* We = (const float*)d_in[2];
    const float* be = (const float*)d_in[3];
    float* out = (float*)d_out;

    static int smem_set = 0;
    const int k4_smem = NSTAGE * STAGE_FLOATS * 4;   // 78336 B
    if (!smem_set) {
        cudaFuncSetAttribute(k4_gemm, cudaFuncAttributeMaxDynamicSharedMemorySize, k4_smem);
        smem_set = 1;
    }

    k1_gate<<<dim3(Vv/128, Bb), 128>>>(x, Wg);
    k2_plan<<<1, 32>>>();
    k3_scatter<<<(NTOK + 255)/256, 256>>>();
    k4_gemm<<<dim3(5, MAX_TILES), 256, k4_smem>>>(We, be);
    k5_out<<<dim3(Vv/32, (Oo + 31)/32, Bb), dim3(32, 8)>>>(out);
}

// round 7
// speedup vs baseline: 2.0461x; 1.0536x over previous
#include <cuda_runtime.h>
#include <cuda_bf16.h>
#include <math.h>
#include <stdint.h>

// Problem constants
#define Bb   64
#define Dd   512
#define Vv   512
#define Oo   720
#define Ee   8
#define NTOK    (Bb*Vv)        // 32768 tokens
#define NASSIGN (NTOK*2)       // 65536 assignments (top_k = 2)
#define TILE_M  128
#define TILE_N  144            // 720 = 5 * 144
#define MAX_TILES (NASSIGN/TILE_M + Ee)   // 520
#define ROWS_CAP  (MAX_TILES*TILE_M)
#define NSTAGE 3
#define NKCHUNK (Dd/32)        // 16
// swizzled stage: (128+144) rows x 128 B
#define STAGE_BYTES ((TILE_M + TILE_N) * 128)   // 34816
#define B_OFF (TILE_M*128)                      // 16384

// ---------------- static device scratch ----------------
__device__ float g_XT[NTOK*Dd];          // tokens [B*V][D], tf32-rounded (RNA)
__device__ float g_part[2][NTOK*Oo];     // per-slot partial outputs
__device__ int   g_rows[ROWS_CAP];
__device__ float g_roww[ROWS_CAP];
__device__ int   g_counts[Ee];           // zero-initialized; k2 re-zeros each call
__device__ int   g_cursor[Ee];
__device__ int   g_tile_e[MAX_TILES];
__device__ int   g_tile_r0[MAX_TILES];
__device__ int   g_ntiles;
__device__ int   g_sel[NASSIGN];
__device__ float g_wsel[NASSIGN];

__device__ __forceinline__ float to_tf32(float x) {
    float r; asm("cvt.rna.tf32.f32 %0, %1;" : "=f"(r) : "f"(x)); return r;
}
__device__ __forceinline__ void cp16(void* smem_ptr, const void* gptr, bool valid) {
    uint32_t saddr = (uint32_t)__cvta_generic_to_shared(smem_ptr);
    int sz = valid ? 16 : 0;
    asm volatile("cp.async.cg.shared.global [%0], [%1], 16, %2;\n"
                 :: "r"(saddr), "l"(gptr), "r"(sz));
}
__device__ __forceinline__ void ldsm4(uint32_t& r0, uint32_t& r1, uint32_t& r2, uint32_t& r3,
                                      uint32_t addr) {
    asm volatile("ldmatrix.sync.aligned.m8n8.x4.shared.b16 {%0,%1,%2,%3}, [%4];"
                 : "=r"(r0), "=r"(r1), "=r"(r2), "=r"(r3) : "r"(addr));
}
__device__ __forceinline__ void ldsm2(uint32_t& r0, uint32_t& r1, uint32_t addr) {
    asm volatile("ldmatrix.sync.aligned.m8n8.x2.shared.b16 {%0,%1}, [%2];"
                 : "=r"(r0), "=r"(r1) : "r"(addr));
}

// ---------------- K1: fused transpose + gating + softmax + top-2 ----------------
__global__ void k1_gate(const float* __restrict__ x, const float* __restrict__ Wg) {
    __shared__ float sWg[Ee*Dd];
    __shared__ float sX[32][129];
    const int b  = blockIdx.y;
    const int v0 = blockIdx.x * 128;
    const int tid = threadIdx.x;
    const int wq = tid >> 5, lane = tid & 31;

    for (int i = tid; i < Ee*Dd; i += 128) sWg[i] = Wg[i];
    __syncthreads();

    float lg[Ee];
#pragma unroll
    for (int e = 0; e < Ee; e++) lg[e] = 0.f;

    for (int dc = 0; dc < Dd/32; dc++) {
#pragma unroll
        for (int i = 0; i < 32; i++)
            sX[i][tid] = x[((size_t)b*Dd + dc*32 + i)*Vv + v0 + tid];
        __syncthreads();
#pragma unroll
        for (int i = 0; i < 32; i++) {
            float xv = sX[i][tid];
            int d = dc*32 + i;
#pragma unroll
            for (int e = 0; e < Ee; e++) lg[e] += xv * sWg[e*Dd + d];
        }
#pragma unroll
        for (int r = 0; r < 32; r++) {
            int v = wq*32 + r;
            g_XT[((size_t)(b*Vv + v0 + v))*Dd + dc*32 + lane] = to_tf32(sX[lane][v]);
        }
        __syncthreads();
    }

    float m = lg[0];
#pragma unroll
    for (int e = 1; e < Ee; e++) m = fmaxf(m, lg[e]);
    float p[Ee], s = 0.f;
#pragma unroll
    for (int e = 0; e < Ee; e++) { p[e] = expf(lg[e] - m); s += p[e]; }
    float inv = 1.f / s;
#pragma unroll
    for (int e = 0; e < Ee; e++) p[e] *= inv;

    int i1 = 0;
#pragma unroll
    for (int e = 1; e < Ee; e++) if (p[e] > p[i1]) i1 = e;
    int i2 = (i1 == 0) ? 1 : 0;
#pragma unroll
    for (int e = 0; e < Ee; e++) if (e != i1 && p[e] > p[i2]) i2 = e;

    int t = b*Vv + v0 + tid;
    g_sel[2*t + 0] = i1;  g_wsel[2*t + 0] = p[i1];
    g_sel[2*t + 1] = i2;  g_wsel[2*t + 1] = p[i2];
    atomicAdd(&g_counts[i1], 1);
    atomicAdd(&g_counts[i2], 1);
}

// ---------------- K2: plan tiles; re-zero counters ----------------
__global__ void k2_plan() {
    if (threadIdx.x != 0 || blockIdx.x != 0) return;
    int base = 0, nt = 0;
    for (int e = 0; e < Ee; e++) {
        int cnt = g_counts[e];
        g_counts[e] = 0;
        g_cursor[e] = base;
        int t = (cnt + TILE_M - 1) / TILE_M;
        for (int i = 0; i < t; i++) { g_tile_e[nt] = e; g_tile_r0[nt] = base + i*TILE_M; nt++; }
        for (int pq = base + cnt; pq < base + t*TILE_M; pq++) g_rows[pq] = -1;
        base += t*TILE_M;
    }
    g_ntiles = nt;
}

// ---------------- K3: block-aggregated scatter ----------------
__global__ void k3_scatter() {
    __shared__ int hcnt[Ee];
    __shared__ int hbase[Ee];
    const int tid = threadIdx.x;
    const int t = blockIdx.x * blockDim.x + tid;
    if (tid < Ee) hcnt[tid] = 0;
    __syncthreads();
    int e1 = 0, e2 = 0, p1 = 0, p2 = 0;
    float w1 = 0.f, w2 = 0.f;
    if (t < NTOK) {
        e1 = g_sel[2*t + 0];  w1 = g_wsel[2*t + 0];
        e2 = g_sel[2*t + 1];  w2 = g_wsel[2*t + 1];
        p1 = atomicAdd(&hcnt[e1], 1);
        p2 = atomicAdd(&hcnt[e2], 1);
    }
    __syncthreads();
    if (tid < Ee) hbase[tid] = atomicAdd(&g_cursor[tid], hcnt[tid]);
    __syncthreads();
    if (t < NTOK) {
        int q1 = hbase[e1] + p1;
        int q2 = hbase[e2] + p2;
        g_rows[q1] = 2*t + 0;  g_roww[q1] = w1;
        g_rows[q2] = 2*t + 1;  g_roww[q2] = w2;
    }
}

// ---------------- K4: grouped GEMM, tf32 mma.sync + ldmatrix, swizzled 3-stage, 2 CTAs/SM ----------------
__global__ __launch_bounds__(256, 2) void k4_gemm(const float* __restrict__ We,
                                                  const float* __restrict__ be) {
    const int mt = blockIdx.y;
    if (mt >= g_ntiles) return;
    const int o0 = blockIdx.x * TILE_N;

    extern __shared__ __align__(128) char sm[];   // NSTAGE * STAGE_BYTES
    __shared__ int   sTok[TILE_M];
    __shared__ float sW[TILE_M];
    __shared__ float sBias[TILE_N];

    const int tid  = threadIdx.x;
    const int lane = tid & 31, w = tid >> 5;
    const int wm = w & 3, wn = w >> 2;          // 4(M) x 2(N); warp tile 32 x 72
    const int g  = lane >> 2, tg = lane & 3;

    const int e  = g_tile_e[mt];
    const int r0 = g_tile_r0[mt];
    const float* WeE = We + (size_t)e*Oo*Dd;

    if (tid < TILE_M) { sTok[tid] = g_rows[r0 + tid]; sW[tid] = g_roww[r0 + tid]; }
    if (tid < TILE_N) sBias[tid] = be[e*Oo + o0 + tid];
    __syncthreads();

    // swizzled stage loader: row r (128B), unit u (16B) -> offset r*128 + ((u^(r&7))<<4)
    auto load_stage = [&](int kc, int st) {
        char* As = sm + st*STAGE_BYTES;
        char* Bs = As + B_OFF;
        const int kb = kc*32;
#pragma unroll
        for (int j = 0; j < 4; j++) {             // A: 128 rows x 8 units
            int q = tid + j*256;
            int r = q >> 3, u = q & 7;
            int tk = sTok[r];
            const float* src = (tk >= 0) ? (g_XT + (size_t)(tk >> 1)*Dd + kb + u*4) : g_XT;
            cp16(As + r*128 + ((u ^ (r & 7)) << 4), src, tk >= 0);
        }
#pragma unroll
        for (int j = 0; j < 5; j++) {             // B: 144 rows x 8 units
            int q = tid + j*256;
            if (q < TILE_N*8) {
                int r = q >> 3, u = q & 7;
                cp16(Bs + r*128 + ((u ^ (r & 7)) << 4),
                     WeE + (size_t)(o0 + r)*Dd + kb + u*4, true);
            }
        }
    };

    // ---- per-lane ldmatrix row bases (byte offsets within a stage) + swizzle keys ----
    const uint32_t sm0 = (uint32_t)__cvta_generic_to_shared(sm);
    const int rA = lane & 7;
    // A: tiles 0,1 -> +0/+8 rows; tiles 2,3 -> +1 unit (4 cols)
    const int aRowSel = ((lane >> 3) & 1) * 8;
    const uint32_t uhA = (lane >> 4) << 4;        // unit offset in bytes (pre-shifted)
    uint32_t aRowOff[2], aXor[2];
#pragma unroll
    for (int mf = 0; mf < 2; mf++) {
        int row = wm*32 + mf*16 + aRowSel + rA;
        aRowOff[mf] = sm0 + row*128;
        aXor[mf] = (uint32_t)((row & 7) << 4);
    }
    // B: tiles 0,1 -> +0/+1 unit; tiles 2,3 -> +8 rows (next nf)
    const int bRowSel = (lane >> 4) * 8;
    const uint32_t uhB = ((lane >> 3) & 1) << 4;
    uint32_t bRowOff[4], bXor[4];
#pragma unroll
    for (int p = 0; p < 4; p++) {
        int row = wn*72 + p*16 + bRowSel + rA;
        bRowOff[p] = sm0 + B_OFF + row*128;
        bXor[p] = (uint32_t)((row & 7) << 4);
    }
    // x2 tile (nf=8): lanes 0-15; lanes 8-15 -> +1 unit
    uint32_t b8RowOff, b8Xor;
    {
        int row = wn*72 + 64 + rA;
        b8RowOff = sm0 + B_OFF + row*128;
        b8Xor = (uint32_t)((row & 7) << 4);
    }

    float acc[2][9][4];
#pragma unroll
    for (int mf = 0; mf < 2; mf++)
#pragma unroll
        for (int nf = 0; nf < 9; nf++)
#pragma unroll
            for (int i = 0; i < 4; i++) acc[mf][nf][i] = 0.f;

    load_stage(0, 0);
    asm volatile("cp.async.commit_group;\n");
    load_stage(1, 1);
    asm volatile("cp.async.commit_group;\n");

    for (int kc = 0; kc < NKCHUNK; kc++) {
        const int st = kc % NSTAGE;
        asm volatile("cp.async.wait_group 1;\n");   // stage kc complete; kc+1 may fly
        __syncthreads();                            // everyone done with stage (kc+2)%3's old data

        if (kc + 2 < NKCHUNK) load_stage(kc + 2, (kc + 2) % NSTAGE);
        asm volatile("cp.async.commit_group;\n");

        const uint32_t stOff = (uint32_t)(st*STAGE_BYTES);

#pragma unroll
        for (int ks = 0; ks < 4; ks++) {
            const uint32_t kuA = uhA + ks*32;       // unit-bytes before swizzle
            const uint32_t kuB = uhB + ks*32;
            uint32_t a[2][4], bf[9][2];
#pragma unroll
            for (int mf = 0; mf < 2; mf++)
                ldsm4(a[mf][0], a[mf][1], a[mf][2], a[mf][3],
                      aRowOff[mf] + stOff + (kuA ^ aXor[mf]));
#pragma unroll
            for (int p = 0; p < 4; p++)
                ldsm4(bf[2*p][0], bf[2*p][1], bf[2*p+1][0], bf[2*p+1][1],
                      bRowOff[p] + stOff + (kuB ^ bXor[p]));
            ldsm2(bf[8][0], bf[8][1], b8RowOff + stOff + (kuB ^ b8Xor));

#pragma unroll
            for (int mf = 0; mf < 2; mf++)
#pragma unroll
                for (int nf = 0; nf < 9; nf++) {
                    float* c = acc[mf][nf];
                    asm volatile(
                        "mma.sync.aligned.m16n8k8.row.col.f32.tf32.tf32.f32 "
                        "{%0,%1,%2,%3}, {%4,%5,%6,%7}, {%8,%9}, {%0,%1,%2,%3};\n"
                        : "+f"(c[0]), "+f"(c[1]), "+f"(c[2]), "+f"(c[3])
                        : "r"(a[mf][0]), "r"(a[mf][1]), "r"(a[mf][2]), "r"(a[mf][3]),
                          "r"(bf[nf][0]), "r"(bf[nf][1]));
                }
        }
    }

    // epilogue: out = coef * (acc + bias) into slot-partial buffers (deterministic)
#pragma unroll
    for (int mf = 0; mf < 2; mf++) {
#pragma unroll
        for (int nf = 0; nf < 9; nf++) {
            int c = wn*72 + nf*8 + tg*2;
            int o = o0 + c;
#pragma unroll
            for (int h = 0; h < 2; h++) {
                int r = wm*32 + mf*16 + g + h*8;
                int tk = sTok[r];
                if (tk < 0) continue;
                float wv = sW[r];
                float2 v;
                v.x = wv * (acc[mf][nf][h*2 + 0] + sBias[c]);
                v.y = wv * (acc[mf][nf][h*2 + 1] + sBias[c + 1]);
                *(float2*)(&g_part[tk & 1][(size_t)(tk >> 1)*Oo + o]) = v;
            }
        }
    }
}

// ---------------- K5: sum slot partials + transpose [B,V,O] -> [B,O,V] ----------------
__global__ void k5_out(float* __restrict__ out) {
    __shared__ float s[32][33];
    const int b = blockIdx.z, v0 = blockIdx.x*32, o0 = blockIdx.y*32;
    const int tx = threadIdx.x, ty = threadIdx.y;
#pragma unroll
    for (int i = 0; i < 4; i++) {
        int vy = ty + i*8;
        int o = o0 + tx;
        if (o < Oo) {
            size_t idx = (size_t)(b*Vv + v0 + vy)*Oo + o;
            s[vy][tx] = g_part[0][idx] + g_part[1][idx];
        }
    }
    __syncthreads();
#pragma unroll
    for (int i = 0; i < 4; i++) {
        int oy = ty + i*8;
        if (o0 + oy < Oo)
            out[((size_t)b*Oo + o0 + oy)*Vv + v0 + tx] = s[tx][oy];
    }
}

// ---------------- launch ----------------
extern "C" void kernel_launch(void* const* d_in, const int* in_sizes, int n_in,
                              void* d_out, int out_size) {
    const float* x  = (const float*)d_in[0];
    const float* Wg = (const float*)d_in[1];
    const float* We = (const float*)d_in[2];
    const float* be = (const float*)d_in[3];
    float* out = (float*)d_out;

    static int smem_set = 0;
    const int k4_smem = NSTAGE * STAGE_BYTES;   // 104448 B
    if (!smem_set) {
        cudaFuncSetAttribute(k4_gemm, cudaFuncAttributeMaxDynamicSharedMemorySize, k4_smem);
        smem_set = 1;
    }

    k1_gate<<<dim3(Vv/128, Bb), 128>>>(x, Wg);
    k2_plan<<<1, 32>>>();
    k3_scatter<<<(NTOK + 255)/256, 256>>>();
    k4_gemm<<<dim3(5, MAX_TILES), 256, k4_smem>>>(We, be);
    k5_out<<<dim3(Vv/32, (Oo + 31)/32, Bb), dim3(32, 8)>>>(out);
}